// round 6
// baseline (speedup 1.0000x reference)
#include <cuda_runtime.h>
#include <math.h>

#define NNODES 100000
#define FIN    128
#define HID    128
#define CLS    64
#define EMAX   2000000

// ---------------- static device scratch ----------------
__device__ float g_h   [(size_t)NNODES * HID];
__device__ float g_emb [(size_t)NNODES * HID];
__device__ float g_h2  [(size_t)NNODES * CLS];
__device__ float g_dinv[NNODES];
__device__ int   g_deg [NNODES];
__device__ int   g_incl[NNODES];
__device__ int   g_bsum[256];
__device__ int   g_rowptr[NNODES + 1];
__device__ int   g_cursor[NNODES];
__device__ int   g_csr_src[EMAX];
__device__ int   g_idx64;

// ---------------- edge-index dtype detection ----------------
__global__ void detect_idx_kernel(const void* __restrict__ ei, int E, int N) {
    if (threadIdx.x != 0 || blockIdx.x != 0) return;
    const long long* p64 = (const long long*)ei;
    int ok = 1;
    for (int i = 0; i < 128 && i < E; i++) {
        long long a = p64[i];
        long long b = p64[(size_t)E + i];
        if (a < 0 || a >= N || b < 0 || b >= N) { ok = 0; break; }
    }
    g_idx64 = ok;
}

__device__ __forceinline__ int fetch_idx(const void* __restrict__ ei, size_t i) {
    if (g_idx64) return (int)((const long long*)ei)[i];
    return ((const int*)ei)[i];
}

__global__ void zero_deg_kernel(int N) {
    int i = blockIdx.x * blockDim.x + threadIdx.x;
    if (i < N) g_deg[i] = 0;
}

__global__ void deg_kernel(const void* __restrict__ ei, int E, int N) {
    int i = blockIdx.x * blockDim.x + threadIdx.x;
    if (i >= E) return;
    int d = fetch_idx(ei, (size_t)E + i);
    if ((unsigned)d < (unsigned)N) atomicAdd(&g_deg[d], 1);
}

// ---------------- prefix scan over degrees ----------------
__global__ __launch_bounds__(1024) void scan1_kernel(int N) {
    __shared__ int sh[1024];
    int i = blockIdx.x * 1024 + threadIdx.x;
    int v = (i < N) ? g_deg[i] : 0;
    sh[threadIdx.x] = v;
    __syncthreads();
    for (int off = 1; off < 1024; off <<= 1) {
        int t = (threadIdx.x >= off) ? sh[threadIdx.x - off] : 0;
        __syncthreads();
        sh[threadIdx.x] += t;
        __syncthreads();
    }
    if (i < N) g_incl[i] = sh[threadIdx.x];
    if (threadIdx.x == 1023) g_bsum[blockIdx.x] = sh[1023];
}

__global__ __launch_bounds__(1024) void scan2_kernel(int nb) {
    __shared__ int sh[1024];
    int v = (threadIdx.x < nb) ? g_bsum[threadIdx.x] : 0;
    sh[threadIdx.x] = v;
    __syncthreads();
    for (int off = 1; off < 1024; off <<= 1) {
        int t = (threadIdx.x >= off) ? sh[threadIdx.x - off] : 0;
        __syncthreads();
        sh[threadIdx.x] += t;
        __syncthreads();
    }
    if (threadIdx.x < nb)
        g_bsum[threadIdx.x] = (threadIdx.x == 0) ? 0 : sh[threadIdx.x - 1];
}

__global__ void scan3_kernel(int N) {
    int i = blockIdx.x * blockDim.x + threadIdx.x;
    if (i >= N) return;
    int deg = g_deg[i];
    int v = g_incl[i] + g_bsum[i >> 10];
    g_rowptr[i + 1] = v;
    g_cursor[i] = v - deg;
    g_dinv[i] = rsqrtf((float)(deg + 1));   // fused dinv
    if (i == 0) g_rowptr[0] = 0;
}

__global__ void fill_csr_kernel(const void* __restrict__ ei, int E, int N) {
    int e = blockIdx.x * blockDim.x + threadIdx.x;
    if (e >= E) return;
    int s = fetch_idx(ei, e);
    int d = fetch_idx(ei, (size_t)E + e);
    if ((unsigned)s >= (unsigned)N || (unsigned)d >= (unsigned)N) return;
    int pos = atomicAdd(&g_cursor[d], 1);
    if (pos < EMAX) g_csr_src[pos] = s;
}

// ---------------- SGEMM: C[M,TN_] = A[M,128] @ B[128,TN_] ----------------
// 128 x TN_ block tile, 256 threads, 8 x (TN_/16) microtile, BK=8, double-buffered.
template <int TN_>
__global__ __launch_bounds__(256)
void gemm_big(const float* __restrict__ A, const float* __restrict__ B,
              float* __restrict__ C, int M) {
    constexpr int TM = 128;
    constexpr int BK = 8;
    constexpr int TNT = TN_ / 16;               // per-thread cols: 8 or 4
    __shared__ float As[2][BK][TM];
    __shared__ float Bs[2][BK][TN_];

    const int t  = threadIdx.x;
    const int tx = t & 15;                       // 0..15 col group
    const int ty = t >> 4;                       // 0..15 row group
    const int rowBase = blockIdx.x * TM;
    const int colBase = blockIdx.y * TN_;

    // A load coords: thread loads one float4; rows = t>>1, k-col = (t&1)*4
    const int aRow = t >> 1;
    const int aK4  = (t & 1) * 4;
    // B load: TN_=128 -> one float4/thread (row=t>>5, col4=t&31)
    //         TN_=64  -> one float2/thread (row=t>>5, col2=t&31)
    const int bRow = t >> 5;
    const int bCol = t & 31;

    float acc[8][TNT];
#pragma unroll
    for (int i = 0; i < 8; i++)
#pragma unroll
        for (int j = 0; j < TNT; j++) acc[i][j] = 0.f;

    // staging regs
    float4 stA;
    float4 stB4; float2 stB2;

    auto loadA = [&](int k0) {
        stA = make_float4(0.f, 0.f, 0.f, 0.f);
        int r = rowBase + aRow;
        if (r < M) stA = *(const float4*)&A[(size_t)r * 128 + k0 + aK4];
    };
    auto loadB = [&](int k0) {
        if (TN_ == 128)
            stB4 = *(const float4*)&B[(size_t)(k0 + bRow) * TN_ + colBase + bCol * 4];
        else
            stB2 = *(const float2*)&B[(size_t)(k0 + bRow) * TN_ + colBase + bCol * 2];
    };
    auto storeTile = [&](int buf) {
        As[buf][aK4 + 0][aRow] = stA.x;
        As[buf][aK4 + 1][aRow] = stA.y;
        As[buf][aK4 + 2][aRow] = stA.z;
        As[buf][aK4 + 3][aRow] = stA.w;
        if (TN_ == 128)
            *(float4*)&Bs[buf][bRow][bCol * 4] = stB4;
        else
            *(float2*)&Bs[buf][bRow][bCol * 2] = stB2;
    };

    loadA(0); loadB(0);
    storeTile(0);
    __syncthreads();

#pragma unroll
    for (int tile = 0; tile < 128 / BK; tile++) {
        const int buf = tile & 1;
        if (tile + 1 < 128 / BK) {
            loadA((tile + 1) * BK);
            loadB((tile + 1) * BK);
        }
#pragma unroll
        for (int kk = 0; kk < BK; kk++) {
            float a[8];
            float b[TNT];
#pragma unroll
            for (int i = 0; i < 8; i += 4)
                *(float4*)&a[i] = *(const float4*)&As[buf][kk][ty * 8 + i];
#pragma unroll
            for (int j = 0; j < TNT; j += 4)
                *(float4*)&b[j] = *(const float4*)&Bs[buf][kk][tx * TNT + j];
#pragma unroll
            for (int i = 0; i < 8; i++)
#pragma unroll
                for (int j = 0; j < TNT; j++)
                    acc[i][j] += a[i] * b[j];
        }
        if (tile + 1 < 128 / BK) {
            storeTile(buf ^ 1);
        }
        __syncthreads();
    }

#pragma unroll
    for (int i = 0; i < 8; i++) {
        int r = rowBase + ty * 8 + i;
        if (r < M) {
#pragma unroll
            for (int j = 0; j < TNT; j += 4)
                *(float4*)&C[(size_t)r * TN_ + colBase + tx * TNT + j] =
                    make_float4(acc[i][j], acc[i][j + 1], acc[i][j + 2], acc[i][j + 3]);
        }
    }
}

// ---------------- layer-1 gather: warp per node, fused self-loop+bias+relu ----
__global__ __launch_bounds__(256)
void gather1_kernel(const float* __restrict__ b1, float* __restrict__ emb_out, int N) {
    int warp = (blockIdx.x * blockDim.x + threadIdx.x) >> 5;
    int lane = threadIdx.x & 31;
    if (warp >= N) return;
    const int i = warp;
    const int start = g_rowptr[i], end = g_rowptr[i + 1];
    const float di = g_dinv[i];

    float4 acc = *(const float4*)&g_h[(size_t)i * 128 + lane * 4];
    float d2 = di * di;
    acc.x *= d2; acc.y *= d2; acc.z *= d2; acc.w *= d2;

    for (int base = start; base < end; base += 32) {
        int rem = end - base;
        int cnt = rem < 32 ? rem : 32;
        int   myidx = (lane < cnt) ? g_csr_src[base + lane] : 0;
        float myw   = (lane < cnt) ? di * g_dinv[myidx] : 0.f;
        for (int j = 0; j < cnt; j++) {
            int   s = __shfl_sync(0xFFFFFFFFu, myidx, j);
            float w = __shfl_sync(0xFFFFFFFFu, myw, j);
            float4 v = *(const float4*)&g_h[(size_t)s * 128 + lane * 4];
            acc.x += v.x * w; acc.y += v.y * w; acc.z += v.z * w; acc.w += v.w * w;
        }
    }
    float4 bv = *(const float4*)&b1[lane * 4];
    acc.x = fmaxf(acc.x + bv.x, 0.f);
    acc.y = fmaxf(acc.y + bv.y, 0.f);
    acc.z = fmaxf(acc.z + bv.z, 0.f);
    acc.w = fmaxf(acc.w + bv.w, 0.f);
    *(float4*)&g_emb[(size_t)i * 128 + lane * 4] = acc;
    if (emb_out) *(float4*)&emb_out[(size_t)i * 128 + lane * 4] = acc;
}

// ---------------- layer-2 gather: warp per node, fused bias+log_softmax -------
__global__ __launch_bounds__(256)
void gather2_kernel(const float* __restrict__ b2, float* __restrict__ out, int N) {
    int warp = (blockIdx.x * blockDim.x + threadIdx.x) >> 5;
    int lane = threadIdx.x & 31;
    if (warp >= N) return;
    const int i = warp;
    const int start = g_rowptr[i], end = g_rowptr[i + 1];
    const float di = g_dinv[i];

    float2 acc = *(const float2*)&g_h2[(size_t)i * 64 + lane * 2];
    float d2 = di * di;
    acc.x *= d2; acc.y *= d2;

    for (int base = start; base < end; base += 32) {
        int rem = end - base;
        int cnt = rem < 32 ? rem : 32;
        int   myidx = (lane < cnt) ? g_csr_src[base + lane] : 0;
        float myw   = (lane < cnt) ? di * g_dinv[myidx] : 0.f;
        for (int j = 0; j < cnt; j++) {
            int   s = __shfl_sync(0xFFFFFFFFu, myidx, j);
            float w = __shfl_sync(0xFFFFFFFFu, myw, j);
            float2 v = *(const float2*)&g_h2[(size_t)s * 64 + lane * 2];
            acc.x += v.x * w; acc.y += v.y * w;
        }
    }
    float2 bv = *(const float2*)&b2[lane * 2];
    acc.x += bv.x; acc.y += bv.y;

    float m = fmaxf(acc.x, acc.y);
#pragma unroll
    for (int o = 16; o > 0; o >>= 1) m = fmaxf(m, __shfl_xor_sync(0xFFFFFFFFu, m, o));
    float sm = __expf(acc.x - m) + __expf(acc.y - m);
#pragma unroll
    for (int o = 16; o > 0; o >>= 1) sm += __shfl_xor_sync(0xFFFFFFFFu, sm, o);
    float lse = m + logf(sm);
    *(float2*)&out[(size_t)i * 64 + lane * 2] = make_float2(acc.x - lse, acc.y - lse);
}

extern "C" void kernel_launch(void* const* d_in, const int* in_sizes, int n_in,
                              void* d_out, int out_size) {
    const float* x  = (const float*)d_in[0];
    const void*  ei = d_in[1];
    const float* W1 = (const float*)d_in[2];
    const float* b1 = (const float*)d_in[3];
    const float* W2 = (const float*)d_in[4];
    const float* b2 = (const float*)d_in[5];
    const int N = in_sizes[0] / FIN;
    const int E = in_sizes[1] / 2;

    float* out_ls  = (float*)d_out;
    float* out_emb = (out_size >= N * (CLS + HID)) ? out_ls + (size_t)N * CLS : nullptr;

    static float* s_h   = nullptr;
    static float* s_emb = nullptr;
    static float* s_h2  = nullptr;
    if (!s_h) {
        cudaGetSymbolAddress((void**)&s_h,   g_h);
        cudaGetSymbolAddress((void**)&s_emb, g_emb);
        cudaGetSymbolAddress((void**)&s_h2,  g_h2);
    }

    const int T = 256;
    const int nScanBlocks = (N + 1023) / 1024;

    // launch #1..#3: setup
    detect_idx_kernel<<<1, 32>>>(ei, E, N);
    zero_deg_kernel<<<(N + T - 1) / T, T>>>(N);
    deg_kernel<<<(E + T - 1) / T, T>>>(ei, E, N);

    // launch #4: h = x @ W1  (placed here so the fixed-index ncu capture hits it)
    {
        dim3 grid((N + 127) / 128, HID / 128);
        gemm_big<HID><<<grid, T>>>(x, W1, s_h, N);
    }

    // launches #5..#8: CSR build (prefix scan + fill; scan3 also computes dinv)
    scan1_kernel<<<nScanBlocks, 1024>>>(N);
    scan2_kernel<<<1, 1024>>>(nScanBlocks);
    scan3_kernel<<<(N + T - 1) / T, T>>>(N);
    fill_csr_kernel<<<(E + T - 1) / T, T>>>(ei, E, N);

    // #9: layer-1 gather (fused self-loop + bias + relu) -> emb
    {
        long long threads = (long long)N * 32;
        gather1_kernel<<<(int)((threads + T - 1) / T), T>>>(b1, out_emb, N);
    }

    // #10: h2 = emb @ W2
    {
        dim3 grid((N + 127) / 128, CLS / 64);
        gemm_big<CLS><<<grid, T>>>(s_emb, W2, s_h2, N);
    }

    // #11: layer-2 gather (fused self-loop + bias + log_softmax) -> out
    {
        long long threads = (long long)N * 32;
        gather2_kernel<<<(int)((threads + T - 1) / T), T>>>(b2, out_ls, N);
    }
}

// round 7
// speedup vs baseline: 1.1523x; 1.1523x over previous
#include <cuda_runtime.h>
#include <math.h>

#define NNODES 100000
#define FIN    128
#define HID    128
#define CLS    64
#define EMAX   2000000

// ---------------- static device scratch ----------------
__device__ float g_h   [(size_t)NNODES * HID];
__device__ float g_emb [(size_t)NNODES * HID];
__device__ float g_h2  [(size_t)NNODES * CLS];
__device__ float g_dinv[NNODES];
__device__ int   g_deg [NNODES];
__device__ int   g_incl[NNODES];
__device__ int   g_bsum[256];
__device__ int   g_rowptr[NNODES + 1];
__device__ int   g_cursor[NNODES];
__device__ int   g_csr_src[EMAX];
__device__ int   g_idx64;

// ---------------- edge-index dtype detection ----------------
__global__ void detect_idx_kernel(const void* __restrict__ ei, int E, int N) {
    if (threadIdx.x != 0 || blockIdx.x != 0) return;
    const long long* p64 = (const long long*)ei;
    int ok = 1;
    for (int i = 0; i < 128 && i < E; i++) {
        long long a = p64[i];
        long long b = p64[(size_t)E + i];
        if (a < 0 || a >= N || b < 0 || b >= N) { ok = 0; break; }
    }
    g_idx64 = ok;
}

__device__ __forceinline__ int fetch_idx(const void* __restrict__ ei, size_t i) {
    if (g_idx64) return (int)((const long long*)ei)[i];
    return ((const int*)ei)[i];
}

__global__ void zero_deg_kernel(int N) {
    int i = blockIdx.x * blockDim.x + threadIdx.x;
    if (i < N) g_deg[i] = 0;
}

__global__ void deg_kernel(const void* __restrict__ ei, int E, int N) {
    int i = blockIdx.x * blockDim.x + threadIdx.x;
    if (i >= E) return;
    int d = fetch_idx(ei, (size_t)E + i);
    if ((unsigned)d < (unsigned)N) atomicAdd(&g_deg[d], 1);
}

// ---------------- prefix scan over degrees ----------------
__global__ __launch_bounds__(1024) void scan1_kernel(int N) {
    __shared__ int sh[1024];
    int i = blockIdx.x * 1024 + threadIdx.x;
    int v = (i < N) ? g_deg[i] : 0;
    sh[threadIdx.x] = v;
    __syncthreads();
    for (int off = 1; off < 1024; off <<= 1) {
        int t = (threadIdx.x >= off) ? sh[threadIdx.x - off] : 0;
        __syncthreads();
        sh[threadIdx.x] += t;
        __syncthreads();
    }
    if (i < N) g_incl[i] = sh[threadIdx.x];
    if (threadIdx.x == 1023) g_bsum[blockIdx.x] = sh[1023];
}

__global__ __launch_bounds__(1024) void scan2_kernel(int nb) {
    __shared__ int sh[1024];
    int v = (threadIdx.x < nb) ? g_bsum[threadIdx.x] : 0;
    sh[threadIdx.x] = v;
    __syncthreads();
    for (int off = 1; off < 1024; off <<= 1) {
        int t = (threadIdx.x >= off) ? sh[threadIdx.x - off] : 0;
        __syncthreads();
        sh[threadIdx.x] += t;
        __syncthreads();
    }
    if (threadIdx.x < nb)
        g_bsum[threadIdx.x] = (threadIdx.x == 0) ? 0 : sh[threadIdx.x - 1];
}

__global__ void scan3_kernel(int N) {
    int i = blockIdx.x * blockDim.x + threadIdx.x;
    if (i >= N) return;
    int deg = g_deg[i];
    int v = g_incl[i] + g_bsum[i >> 10];
    g_rowptr[i + 1] = v;
    g_cursor[i] = v - deg;
    g_dinv[i] = rsqrtf((float)(deg + 1));
    if (i == 0) g_rowptr[0] = 0;
}

__global__ void fill_csr_kernel(const void* __restrict__ ei, int E, int N) {
    int e = blockIdx.x * blockDim.x + threadIdx.x;
    if (e >= E) return;
    int s = fetch_idx(ei, e);
    int d = fetch_idx(ei, (size_t)E + e);
    if ((unsigned)s >= (unsigned)N || (unsigned)d >= (unsigned)N) return;
    int pos = atomicAdd(&g_cursor[d], 1);
    if (pos < EMAX) g_csr_src[pos] = s;
}

// ---------------- tensor-core helpers (3xtf32) ----------------
__device__ __forceinline__ void split_tf32(float v, unsigned& hi, unsigned& lo) {
    asm("cvt.rna.tf32.f32 %0, %1;" : "=r"(hi) : "f"(v));
    float r = v - __uint_as_float(hi);
    asm("cvt.rna.tf32.f32 %0, %1;" : "=r"(lo) : "f"(r));
}

__device__ __forceinline__ void mma_tf32(float* d, const unsigned* a, const unsigned* b) {
    asm volatile(
        "mma.sync.aligned.m16n8k8.row.col.f32.tf32.tf32.f32 "
        "{%0,%1,%2,%3}, {%4,%5,%6,%7}, {%8,%9}, {%0,%1,%2,%3};"
        : "+f"(d[0]), "+f"(d[1]), "+f"(d[2]), "+f"(d[3])
        : "r"(a[0]), "r"(a[1]), "r"(a[2]), "r"(a[3]), "r"(b[0]), "r"(b[1]));
}

// ---------------- GEMM via tensor cores, 3xtf32 for fp32 accuracy ----------------
// C[M,NC] = A[M,128] @ B[128,NC].  Block tile 128x64, 256 thr (warps 4m x 2n),
// warp tile 32x32 (mt=2 m16, nt=4 n8), BK=16 double-buffered.
template <int NC>
__global__ __launch_bounds__(256)
void gemm_tc(const float* __restrict__ A, const float* __restrict__ B,
             float* __restrict__ C, int M) {
    constexpr int BK = 16;
    __shared__ float As[2][128][BK + 4];   // stride 20 words -> conflict-free frags
    __shared__ float Bs[2][BK][64 + 4];    // stride 68 words -> <=2-way

    const int t    = threadIdx.x;
    const int lane = t & 31;
    const int grp  = lane >> 2, qid = lane & 3;
    const int warp = t >> 5;
    const int warpM = warp & 3, warpN = warp >> 2;
    const int rowBase = blockIdx.x * 128;
    const int colBase = blockIdx.y * 64;

    float acc[2][4][4];
#pragma unroll
    for (int mt = 0; mt < 2; mt++)
#pragma unroll
        for (int nt = 0; nt < 4; nt++)
#pragma unroll
            for (int k = 0; k < 4; k++) acc[mt][nt][k] = 0.f;

    float4 sa[2], sb;
    auto ldA = [&](int k0) {
#pragma unroll
        for (int i = 0; i < 2; i++) {
            int idx = t + 256 * i;
            int r = rowBase + (idx >> 2);
            int c = (idx & 3) * 4;
            sa[i] = (r < M) ? *(const float4*)&A[(size_t)r * 128 + k0 + c]
                            : make_float4(0.f, 0.f, 0.f, 0.f);
        }
    };
    auto ldB = [&](int k0) {
        int r = k0 + (t >> 4);
        int c = colBase + (t & 15) * 4;
        sb = *(const float4*)&B[(size_t)r * NC + c];
    };
    auto stStage = [&](int buf) {
#pragma unroll
        for (int i = 0; i < 2; i++) {
            int idx = t + 256 * i;
            *(float4*)&As[buf][idx >> 2][(idx & 3) * 4] = sa[i];
        }
        *(float4*)&Bs[buf][t >> 4][(t & 15) * 4] = sb;
    };

    ldA(0); ldB(0);
    stStage(0);
    __syncthreads();

    for (int stage = 0; stage < 128 / BK; stage++) {
        const int buf = stage & 1;
        if (stage + 1 < 128 / BK) { ldA((stage + 1) * BK); ldB((stage + 1) * BK); }
#pragma unroll
        for (int ks = 0; ks < BK / 8; ks++) {
            unsigned ah[2][4], al[2][4], bh[4][2], bl[4][2];
#pragma unroll
            for (int mt = 0; mt < 2; mt++) {
                int r0 = warpM * 32 + mt * 16 + grp;
                int c  = ks * 8 + qid;
                split_tf32(As[buf][r0][c],         ah[mt][0], al[mt][0]);
                split_tf32(As[buf][r0 + 8][c],     ah[mt][1], al[mt][1]);
                split_tf32(As[buf][r0][c + 4],     ah[mt][2], al[mt][2]);
                split_tf32(As[buf][r0 + 8][c + 4], ah[mt][3], al[mt][3]);
            }
#pragma unroll
            for (int nt = 0; nt < 4; nt++) {
                int n0 = warpN * 32 + nt * 8 + grp;
                int k  = ks * 8 + qid;
                split_tf32(Bs[buf][k][n0],     bh[nt][0], bl[nt][0]);
                split_tf32(Bs[buf][k + 4][n0], bh[nt][1], bl[nt][1]);
            }
#pragma unroll
            for (int mt = 0; mt < 2; mt++)
#pragma unroll
                for (int nt = 0; nt < 4; nt++) {
                    mma_tf32(acc[mt][nt], ah[mt], bh[nt]);
                    mma_tf32(acc[mt][nt], ah[mt], bl[nt]);
                    mma_tf32(acc[mt][nt], al[mt], bh[nt]);
                }
        }
        if (stage + 1 < 128 / BK) stStage(buf ^ 1);
        __syncthreads();
    }

#pragma unroll
    for (int mt = 0; mt < 2; mt++)
#pragma unroll
        for (int nt = 0; nt < 4; nt++) {
            int r0 = rowBase + warpM * 32 + mt * 16 + grp;
            int cc = colBase + warpN * 32 + nt * 8 + qid * 2;
            if (r0 < M)
                *(float2*)&C[(size_t)r0 * NC + cc] =
                    make_float2(acc[mt][nt][0], acc[mt][nt][1]);
            if (r0 + 8 < M)
                *(float2*)&C[(size_t)(r0 + 8) * NC + cc] =
                    make_float2(acc[mt][nt][2], acc[mt][nt][3]);
        }
}

// ---------------- layer-1 gather: warp per node, fused self-loop+bias+relu ----
__global__ __launch_bounds__(256)
void gather1_kernel(const float* __restrict__ b1, float* __restrict__ emb_out, int N) {
    int warp = (blockIdx.x * blockDim.x + threadIdx.x) >> 5;
    int lane = threadIdx.x & 31;
    if (warp >= N) return;
    const int i = warp;
    const int start = g_rowptr[i], end = g_rowptr[i + 1];
    const float di = g_dinv[i];

    float4 acc = *(const float4*)&g_h[(size_t)i * 128 + lane * 4];
    float d2 = di * di;
    acc.x *= d2; acc.y *= d2; acc.z *= d2; acc.w *= d2;

    for (int base = start; base < end; base += 32) {
        int rem = end - base;
        int cnt = rem < 32 ? rem : 32;
        int   myidx = (lane < cnt) ? g_csr_src[base + lane] : 0;
        float myw   = (lane < cnt) ? di * g_dinv[myidx] : 0.f;
        for (int j = 0; j < cnt; j++) {
            int   s = __shfl_sync(0xFFFFFFFFu, myidx, j);
            float w = __shfl_sync(0xFFFFFFFFu, myw, j);
            float4 v = *(const float4*)&g_h[(size_t)s * 128 + lane * 4];
            acc.x += v.x * w; acc.y += v.y * w; acc.z += v.z * w; acc.w += v.w * w;
        }
    }
    float4 bv = *(const float4*)&b1[lane * 4];
    acc.x = fmaxf(acc.x + bv.x, 0.f);
    acc.y = fmaxf(acc.y + bv.y, 0.f);
    acc.z = fmaxf(acc.z + bv.z, 0.f);
    acc.w = fmaxf(acc.w + bv.w, 0.f);
    *(float4*)&g_emb[(size_t)i * 128 + lane * 4] = acc;
    if (emb_out) *(float4*)&emb_out[(size_t)i * 128 + lane * 4] = acc;
}

// ---------------- layer-2 gather: warp per node, fused bias+log_softmax -------
__global__ __launch_bounds__(256)
void gather2_kernel(const float* __restrict__ b2, float* __restrict__ out, int N) {
    int warp = (blockIdx.x * blockDim.x + threadIdx.x) >> 5;
    int lane = threadIdx.x & 31;
    if (warp >= N) return;
    const int i = warp;
    const int start = g_rowptr[i], end = g_rowptr[i + 1];
    const float di = g_dinv[i];

    float2 acc = *(const float2*)&g_h2[(size_t)i * 64 + lane * 2];
    float d2 = di * di;
    acc.x *= d2; acc.y *= d2;

    for (int base = start; base < end; base += 32) {
        int rem = end - base;
        int cnt = rem < 32 ? rem : 32;
        int   myidx = (lane < cnt) ? g_csr_src[base + lane] : 0;
        float myw   = (lane < cnt) ? di * g_dinv[myidx] : 0.f;
        for (int j = 0; j < cnt; j++) {
            int   s = __shfl_sync(0xFFFFFFFFu, myidx, j);
            float w = __shfl_sync(0xFFFFFFFFu, myw, j);
            float2 v = *(const float2*)&g_h2[(size_t)s * 64 + lane * 2];
            acc.x += v.x * w; acc.y += v.y * w;
        }
    }
    float2 bv = *(const float2*)&b2[lane * 2];
    acc.x += bv.x; acc.y += bv.y;

    float m = fmaxf(acc.x, acc.y);
#pragma unroll
    for (int o = 16; o > 0; o >>= 1) m = fmaxf(m, __shfl_xor_sync(0xFFFFFFFFu, m, o));
    float sm = __expf(acc.x - m) + __expf(acc.y - m);
#pragma unroll
    for (int o = 16; o > 0; o >>= 1) sm += __shfl_xor_sync(0xFFFFFFFFu, sm, o);
    float lse = m + logf(sm);
    *(float2*)&out[(size_t)i * 64 + lane * 2] = make_float2(acc.x - lse, acc.y - lse);
}

extern "C" void kernel_launch(void* const* d_in, const int* in_sizes, int n_in,
                              void* d_out, int out_size) {
    const float* x  = (const float*)d_in[0];
    const void*  ei = d_in[1];
    const float* W1 = (const float*)d_in[2];
    const float* b1 = (const float*)d_in[3];
    const float* W2 = (const float*)d_in[4];
    const float* b2 = (const float*)d_in[5];
    const int N = in_sizes[0] / FIN;
    const int E = in_sizes[1] / 2;

    float* out_ls  = (float*)d_out;
    float* out_emb = (out_size >= N * (CLS + HID)) ? out_ls + (size_t)N * CLS : nullptr;

    static float* s_h   = nullptr;
    static float* s_emb = nullptr;
    static float* s_h2  = nullptr;
    if (!s_h) {
        cudaGetSymbolAddress((void**)&s_h,   g_h);
        cudaGetSymbolAddress((void**)&s_emb, g_emb);
        cudaGetSymbolAddress((void**)&s_h2,  g_h2);
    }

    const int T = 256;
    const int nScanBlocks = (N + 1023) / 1024;

    // #1..#3: setup
    detect_idx_kernel<<<1, 32>>>(ei, E, N);
    zero_deg_kernel<<<(N + T - 1) / T, T>>>(N);
    deg_kernel<<<(E + T - 1) / T, T>>>(ei, E, N);

    // #4: h = x @ W1  (tensor cores; slot 4 = the launch ncu captures)
    {
        dim3 grid((N + 127) / 128, HID / 64);
        gemm_tc<HID><<<grid, T>>>(x, W1, s_h, N);
    }

    // #5..#8: CSR build
    scan1_kernel<<<nScanBlocks, 1024>>>(N);
    scan2_kernel<<<1, 1024>>>(nScanBlocks);
    scan3_kernel<<<(N + T - 1) / T, T>>>(N);
    fill_csr_kernel<<<(E + T - 1) / T, T>>>(ei, E, N);

    // #9: layer-1 gather (fused self-loop + bias + relu) -> emb
    {
        long long threads = (long long)N * 32;
        gather1_kernel<<<(int)((threads + T - 1) / T), T>>>(b1, out_emb, N);
    }

    // #10: h2 = emb @ W2 (tensor cores)
    {
        dim3 grid((N + 127) / 128, CLS / 64);
        gemm_tc<CLS><<<grid, T>>>(s_emb, W2, s_h2, N);
    }

    // #11: layer-2 gather (fused self-loop + bias + log_softmax) -> out
    {
        long long threads = (long long)N * 32;
        gather2_kernel<<<(int)((threads + T - 1) / T), T>>>(b2, out_ls, N);
    }
}